// round 3
// baseline (speedup 1.0000x reference)
#include <cuda_runtime.h>
#include <math.h>

#define THREADS 256
#define LEADS   12
#define NB      4
#define ROWS    (NB * LEADS)      // 48
#define F_IN    512
#define HID     256
#define OUTF    128
#define KT      8
#define B_TOTAL 16384

// shared memory layout (floats)
#define XS_FLOATS (ROWS * F_IN)            // 24576  (reused as H buffer, 48x256)
#define WB_FLOATS (2 * KT * HID)           // 4096   (double-buffered weight tile)
#define AS_OFF    (XS_FLOATS + WB_FLOATS)
#define SMEM_FLOATS (AS_OFF + 160)

// ---------------------------------------------------------------------------
// GEMM: C(48 x N) = inp(48 x K, smem, row stride K) @ Wg(K x N, gmem)
// Thread map: 64 column-groups (NT cols each) x 4 row-groups (12 rows each).
// Each thread accumulates all 12 leads of one batch for its NT columns.
// ---------------------------------------------------------------------------
template<int K, int N, int NT>
__device__ __forceinline__ void gemm48(const float* __restrict__ inp,
                                       const float* __restrict__ Wg,
                                       float* __restrict__ Wb,
                                       int tid, int colg, int rowbase,
                                       float (&acc)[LEADS][NT])
{
    constexpr int VLOADS = (KT * N) / (THREADS * 4);  // float4 stage loads/thread
    constexpr int NTILES = K / KT;

    #pragma unroll
    for (int m = 0; m < LEADS; m++)
        #pragma unroll
        for (int c = 0; c < NT; c++) acc[m][c] = 0.f;

    // stage tile 0 into buffer 0
    {
        const float4* Ws = (const float4*)Wg;
        float4* Wd = (float4*)Wb;
        float4 rv[VLOADS];
        #pragma unroll
        for (int i = 0; i < VLOADS; i++) rv[i] = Ws[i * THREADS + tid];
        #pragma unroll
        for (int i = 0; i < VLOADS; i++) Wd[i * THREADS + tid] = rv[i];
    }
    __syncthreads();

    #pragma unroll 1
    for (int t = 0; t < NTILES; t++) {
        float4 rv[VLOADS];
        if (t + 1 < NTILES) {
            const float4* Wn = (const float4*)(Wg + (size_t)(t + 1) * (KT * N));
            #pragma unroll
            for (int i = 0; i < VLOADS; i++) rv[i] = Wn[i * THREADS + tid];
        }

        const float* Wc = Wb + (t & 1) * (KT * N);
        const float* xrow = inp + rowbase * K + t * KT;

        #pragma unroll
        for (int kk = 0; kk < KT; kk += 4) {
            // weights for rows kk..kk+3, this thread's NT columns
            float w[4][NT];
            #pragma unroll
            for (int j = 0; j < 4; j++) {
                if constexpr (NT == 4) {
                    float4 t4 = *(const float4*)&Wc[(kk + j) * N + NT * colg];
                    w[j][0] = t4.x; w[j][1] = t4.y; w[j][2] = t4.z; w[j][3] = t4.w;
                } else {
                    float2 t2 = *(const float2*)&Wc[(kk + j) * N + NT * colg];
                    w[j][0] = t2.x; w[j][1] = t2.y;
                }
            }
            #pragma unroll
            for (int m = 0; m < LEADS; m++) {
                float4 xm = *(const float4*)&xrow[m * K + kk];   // warp-broadcast LDS
                float xs[4] = {xm.x, xm.y, xm.z, xm.w};
                #pragma unroll
                for (int j = 0; j < 4; j++)
                    #pragma unroll
                    for (int c = 0; c < NT; c++)
                        acc[m][c] = fmaf(xs[j], w[j][c], acc[m][c]);
            }
        }

        if (t + 1 < NTILES) {
            float4* Wd = (float4*)(Wb + ((t + 1) & 1) * (KT * N));
            #pragma unroll
            for (int i = 0; i < VLOADS; i++) Wd[i * THREADS + tid] = rv[i];
        }
        __syncthreads();
    }
}

// ---------------------------------------------------------------------------
// Node mixing: H[n] = (relu)( sum_m A[n,m]*acc[m] + b ), stored to smem H
// (stride HID). All 12 leads of this thread's batch live in registers.
// ---------------------------------------------------------------------------
template<int NT, bool RELU>
__device__ __forceinline__ void mix_store(const float (&acc)[LEADS][NT],
                                          const float* __restrict__ As,
                                          const float* __restrict__ bg,
                                          float* __restrict__ Hs,
                                          int colg, int rowg)
{
    float bv[NT];
    #pragma unroll
    for (int c = 0; c < NT; c++) bv[c] = bg[NT * colg + c];

    #pragma unroll
    for (int n = 0; n < LEADS; n++) {
        float h[NT];
        #pragma unroll
        for (int c = 0; c < NT; c++) h[c] = bv[c];
        #pragma unroll
        for (int m = 0; m < LEADS; m++) {
            float a = As[n * LEADS + m];
            #pragma unroll
            for (int c = 0; c < NT; c++) h[c] = fmaf(a, acc[m][c], h[c]);
        }
        if (RELU) {
            #pragma unroll
            for (int c = 0; c < NT; c++) h[c] = fmaxf(h[c], 0.f);
        }
        #pragma unroll
        for (int c = 0; c < NT; c++)
            Hs[(rowg * LEADS + n) * HID + NT * colg + c] = h[c];
    }
}

__global__ void __launch_bounds__(THREADS, 1)
ecg_fused_kernel(const float* __restrict__ x,
                 const float* __restrict__ W1, const float* __restrict__ b1,
                 const float* __restrict__ W2, const float* __restrict__ b2,
                 const float* __restrict__ W3, const float* __restrict__ b3,
                 float* __restrict__ out)
{
    extern __shared__ float smem[];
    float* Xs = smem;                 // X tile, later aliased as H tile (48x256)
    float* Wb = smem + XS_FLOATS;     // weight double buffer
    float* As = smem + AS_OFF;        // normalized adjacency 12x12

    const int tid  = threadIdx.x;
    const int colg = tid & 63;
    const int rowg = tid >> 6;
    const long long batch0 = (long long)blockIdx.x * NB;

    // Build A_norm = D^{-1/2} (adj + 2I) D^{-1/2}  (tiny; one thread)
    if (tid == 0) {
        const signed char ei[15] = {0,0,1,0,1,2,0,1,1,2,6,7,8,9,10};
        const signed char ej[15] = {1,2,2,3,3,3,4,4,5,5,7,8,9,10,11};
        for (int k = 0; k < 144; k++) As[k] = 0.f;
        for (int e = 0; e < 15; e++) {
            As[ei[e] * LEADS + ej[e]] = 1.f;
            As[ej[e] * LEADS + ei[e]] = 1.f;
        }
        for (int i = 0; i < LEADS; i++) As[i * LEADS + i] = 2.f;
        float dinv[LEADS];
        for (int i = 0; i < LEADS; i++) {
            float s = 0.f;
            for (int j = 0; j < LEADS; j++) s += As[i * LEADS + j];
            dinv[i] = 1.0f / sqrtf(s);
        }
        for (int i = 0; i < LEADS; i++)
            for (int j = 0; j < LEADS; j++)
                As[i * LEADS + j] *= dinv[i] * dinv[j];
    }

    // Load X tile (48 x 512) — contiguous region, float4 coalesced
    {
        const float4* xg = (const float4*)(x + batch0 * (LEADS * F_IN));
        float4* xd = (float4*)Xs;
        #pragma unroll
        for (int i = 0; i < (ROWS * F_IN / 4) / THREADS; i++)
            xd[i * THREADS + tid] = xg[i * THREADS + tid];
    }
    __syncthreads();

    float acc[LEADS][4];

    // Layer 1: relu(A @ (X W1) + b1)
    gemm48<F_IN, HID, 4>(Xs, W1, Wb, tid, colg, rowg * LEADS, acc);
    mix_store<4, true>(acc, As, b1, Xs, colg, rowg);   // H1 overlays Xs
    __syncthreads();

    // Layer 2: relu(A @ (H1 W2) + b2)
    gemm48<HID, HID, 4>(Xs, W2, Wb, tid, colg, rowg * LEADS, acc);
    mix_store<4, true>(acc, As, b2, Xs, colg, rowg);   // H2 overlays Xs
    __syncthreads();

    // Layer 3: A @ (H2 W3) + b3, then mean/max pool over leads (register-local)
    float acc3[LEADS][2];
    gemm48<HID, OUTF, 2>(Xs, W3, Wb, tid, colg, rowg * LEADS, acc3);
    {
        const float b3a = b3[2 * colg];
        const float b3b = b3[2 * colg + 1];
        float mean0 = 0.f, mean1 = 0.f;
        float max0 = -INFINITY, max1 = -INFINITY;
        #pragma unroll
        for (int n = 0; n < LEADS; n++) {
            float h0 = b3a, h1 = b3b;
            #pragma unroll
            for (int m = 0; m < LEADS; m++) {
                float a = As[n * LEADS + m];
                h0 = fmaf(a, acc3[m][0], h0);
                h1 = fmaf(a, acc3[m][1], h1);
            }
            mean0 += h0; mean1 += h1;
            max0 = fmaxf(max0, h0); max1 = fmaxf(max1, h1);
        }
        mean0 *= (1.f / 12.f);
        mean1 *= (1.f / 12.f);

        const long long b = batch0 + rowg;
        float* ob = out + b * (2 * OUTF);
        *(float2*)(ob + 2 * colg)        = make_float2(mean0, mean1);
        *(float2*)(ob + OUTF + 2 * colg) = make_float2(max0, max1);
    }
}

extern "C" void kernel_launch(void* const* d_in, const int* in_sizes, int n_in,
                              void* d_out, int out_size)
{
    const float* x  = (const float*)d_in[0];
    const float* W1 = (const float*)d_in[1];
    const float* b1 = (const float*)d_in[2];
    const float* W2 = (const float*)d_in[3];
    const float* b2 = (const float*)d_in[4];
    const float* W3 = (const float*)d_in[5];
    const float* b3 = (const float*)d_in[6];
    float* out = (float*)d_out;

    const size_t smem_bytes = SMEM_FLOATS * sizeof(float);  // ~115.9 KB
    cudaFuncSetAttribute(ecg_fused_kernel,
                         cudaFuncAttributeMaxDynamicSharedMemorySize,
                         (int)smem_bytes);

    ecg_fused_kernel<<<B_TOTAL / NB, THREADS, smem_bytes>>>(
        x, W1, b1, W2, b2, W3, b3, out);
}

// round 4
// speedup vs baseline: 1.0697x; 1.0697x over previous
#include <cuda_runtime.h>
#include <math.h>

#define THREADS 512
#define LEADS   12
#define NB      8
#define ROWS    (NB * LEADS)      // 96
#define F_IN    512
#define HID     256
#define OUTF    128
#define KT      8
#define B_TOTAL 16384

// shared memory layout (floats)
#define XS_FLOATS (ROWS * F_IN)            // 49152 (reused as H buffer, 96x256)
#define WB_FLOATS (2 * KT * HID)           // 4096  (double-buffered weight tile)
#define AS_OFF    (XS_FLOATS + WB_FLOATS)
#define SMEM_FLOATS (AS_OFF + 160)         // 53408 floats = 213,632 B

// ---------------------------------------------------------------------------
// cp.async helpers (LDGSTS) — 16B copies, grouped
// ---------------------------------------------------------------------------
__device__ __forceinline__ void cp_async16(float* smem_dst, const float* gmem_src)
{
    unsigned s = (unsigned)__cvta_generic_to_shared(smem_dst);
    asm volatile("cp.async.ca.shared.global [%0], [%1], 16;\n" :: "r"(s), "l"(gmem_src));
}
__device__ __forceinline__ void cp_async_commit()
{
    asm volatile("cp.async.commit_group;\n");
}
__device__ __forceinline__ void cp_async_wait_all()
{
    asm volatile("cp.async.wait_group 0;\n");
}

// ---------------------------------------------------------------------------
// GEMM: C(96 x N) = inp(96 x K, smem, row stride K) @ Wg(K x N, gmem)
// Thread map: 64 column-groups (NT cols each) x 8 row-groups (12 leads each).
// Each thread accumulates all 12 leads of one batch for its NT columns.
// Weight tiles double-buffered in smem via cp.async.
// ---------------------------------------------------------------------------
template<int K, int N, int NT>
__device__ __forceinline__ void gemm96(const float* __restrict__ inp,
                                       const float* __restrict__ Wg,
                                       float* __restrict__ Wb,
                                       int tid, int colg, int rowbase,
                                       float (&acc)[LEADS][NT])
{
    constexpr int TOT4   = (KT * N) / 4;     // float4 copies per tile (512 or 256)
    constexpr int NTILES = K / KT;

    #pragma unroll
    for (int m = 0; m < LEADS; m++)
        #pragma unroll
        for (int c = 0; c < NT; c++) acc[m][c] = 0.f;

    // stage tile 0 into buffer 0
    if (tid < TOT4) cp_async16(Wb + 4 * tid, Wg + 4 * tid);
    cp_async_commit();

    #pragma unroll 1
    for (int t = 0; t < NTILES; t++) {
        cp_async_wait_all();
        __syncthreads();   // tile t visible; buffer (t+1)&1 free for restage

        if (t + 1 < NTILES) {
            float* dst = Wb + ((t + 1) & 1) * (KT * N);
            const float* src = Wg + (size_t)(t + 1) * (KT * N);
            if (tid < TOT4) cp_async16(dst + 4 * tid, src + 4 * tid);
            cp_async_commit();
        }

        const float* Wc   = Wb + (t & 1) * (KT * N);
        const float* xrow = inp + rowbase * K + t * KT;

        #pragma unroll
        for (int kk = 0; kk < KT; kk += 4) {
            // weights for rows kk..kk+3, this thread's NT columns
            float w[4][NT];
            #pragma unroll
            for (int j = 0; j < 4; j++) {
                if constexpr (NT == 4) {
                    float4 t4 = *(const float4*)&Wc[(kk + j) * N + NT * colg];
                    w[j][0] = t4.x; w[j][1] = t4.y; w[j][2] = t4.z; w[j][3] = t4.w;
                } else {
                    float2 t2 = *(const float2*)&Wc[(kk + j) * N + NT * colg];
                    w[j][0] = t2.x; w[j][1] = t2.y;
                }
            }
            #pragma unroll
            for (int m = 0; m < LEADS; m++) {
                float4 xm = *(const float4*)&xrow[m * K + kk];   // warp-broadcast LDS
                float xs[4] = {xm.x, xm.y, xm.z, xm.w};
                #pragma unroll
                for (int j = 0; j < 4; j++)
                    #pragma unroll
                    for (int c = 0; c < NT; c++)
                        acc[m][c] = fmaf(xs[j], w[j][c], acc[m][c]);
            }
        }
    }
    __syncthreads();   // all threads done reading inp before caller overwrites it
}

// ---------------------------------------------------------------------------
// Node mixing: H[n] = (relu)( sum_m A[n,m]*acc[m] + b ), stored to smem H
// (stride HID). All 12 leads of this thread's batch live in registers.
// ---------------------------------------------------------------------------
template<int NT, bool RELU>
__device__ __forceinline__ void mix_store(const float (&acc)[LEADS][NT],
                                          const float* __restrict__ As,
                                          const float* __restrict__ bg,
                                          float* __restrict__ Hs,
                                          int colg, int rowg)
{
    float bv[NT];
    #pragma unroll
    for (int c = 0; c < NT; c++) bv[c] = bg[NT * colg + c];

    #pragma unroll
    for (int n = 0; n < LEADS; n++) {
        float h[NT];
        #pragma unroll
        for (int c = 0; c < NT; c++) h[c] = bv[c];
        #pragma unroll
        for (int m = 0; m < LEADS; m++) {
            float a = As[n * LEADS + m];
            #pragma unroll
            for (int c = 0; c < NT; c++) h[c] = fmaf(a, acc[m][c], h[c]);
        }
        if (RELU) {
            #pragma unroll
            for (int c = 0; c < NT; c++) h[c] = fmaxf(h[c], 0.f);
        }
        #pragma unroll
        for (int c = 0; c < NT; c++)
            Hs[(rowg * LEADS + n) * HID + NT * colg + c] = h[c];
    }
}

__global__ void __launch_bounds__(THREADS, 1)
ecg_fused_kernel(const float* __restrict__ x,
                 const float* __restrict__ W1, const float* __restrict__ b1,
                 const float* __restrict__ W2, const float* __restrict__ b2,
                 const float* __restrict__ W3, const float* __restrict__ b3,
                 float* __restrict__ out)
{
    extern __shared__ float smem[];
    float* Xs = smem;                 // X tile, later aliased as H tile (96x256)
    float* Wb = smem + XS_FLOATS;     // weight double buffer
    float* As = smem + AS_OFF;        // normalized adjacency 12x12

    const int tid  = threadIdx.x;
    const int colg = tid & 63;
    const int rowg = tid >> 6;        // 0..7
    const long long batch0 = (long long)blockIdx.x * NB;

    // Build A_norm = D^{-1/2} (adj + 2I) D^{-1/2}  (tiny; one thread)
    if (tid == 0) {
        const signed char ei[15] = {0,0,1,0,1,2,0,1,1,2,6,7,8,9,10};
        const signed char ej[15] = {1,2,2,3,3,3,4,4,5,5,7,8,9,10,11};
        for (int k = 0; k < 144; k++) As[k] = 0.f;
        for (int e = 0; e < 15; e++) {
            As[ei[e] * LEADS + ej[e]] = 1.f;
            As[ej[e] * LEADS + ei[e]] = 1.f;
        }
        for (int i = 0; i < LEADS; i++) As[i * LEADS + i] = 2.f;
        float dinv[LEADS];
        for (int i = 0; i < LEADS; i++) {
            float s = 0.f;
            for (int j = 0; j < LEADS; j++) s += As[i * LEADS + j];
            dinv[i] = 1.0f / sqrtf(s);
        }
        for (int i = 0; i < LEADS; i++)
            for (int j = 0; j < LEADS; j++)
                As[i * LEADS + j] *= dinv[i] * dinv[j];
    }

    // Load X tile (96 x 512) — contiguous region, cp.async 16B coalesced
    {
        const float* xg = x + batch0 * (LEADS * F_IN);
        #pragma unroll
        for (int i = 0; i < (ROWS * F_IN / 4) / THREADS; i++)
            cp_async16(Xs + 4 * (i * THREADS + tid), xg + 4 * (i * THREADS + tid));
        cp_async_commit();
        cp_async_wait_all();
    }
    __syncthreads();

    float acc[LEADS][4];

    // Layer 1: relu(A @ (X W1) + b1)
    gemm96<F_IN, HID, 4>(Xs, W1, Wb, tid, colg, rowg * LEADS, acc);
    mix_store<4, true>(acc, As, b1, Xs, colg, rowg);   // H1 overlays Xs
    __syncthreads();

    // Layer 2: relu(A @ (H1 W2) + b2)
    gemm96<HID, HID, 4>(Xs, W2, Wb, tid, colg, rowg * LEADS, acc);
    mix_store<4, true>(acc, As, b2, Xs, colg, rowg);   // H2 overlays Xs
    __syncthreads();

    // Layer 3: A @ (H2 W3) + b3, then mean/max pool over leads (register-local)
    float acc3[LEADS][2];
    gemm96<HID, OUTF, 2>(Xs, W3, Wb, tid, colg, rowg * LEADS, acc3);
    {
        const float b3a = b3[2 * colg];
        const float b3b = b3[2 * colg + 1];
        float mean0 = 0.f, mean1 = 0.f;
        float max0 = -INFINITY, max1 = -INFINITY;
        #pragma unroll
        for (int n = 0; n < LEADS; n++) {
            float h0 = b3a, h1 = b3b;
            #pragma unroll
            for (int m = 0; m < LEADS; m++) {
                float a = As[n * LEADS + m];
                h0 = fmaf(a, acc3[m][0], h0);
                h1 = fmaf(a, acc3[m][1], h1);
            }
            mean0 += h0; mean1 += h1;
            max0 = fmaxf(max0, h0); max1 = fmaxf(max1, h1);
        }
        mean0 *= (1.f / 12.f);
        mean1 *= (1.f / 12.f);

        const long long b = batch0 + rowg;
        float* ob = out + b * (2 * OUTF);
        *(float2*)(ob + 2 * colg)        = make_float2(mean0, mean1);
        *(float2*)(ob + OUTF + 2 * colg) = make_float2(max0, max1);
    }
}

extern "C" void kernel_launch(void* const* d_in, const int* in_sizes, int n_in,
                              void* d_out, int out_size)
{
    const float* x  = (const float*)d_in[0];
    const float* W1 = (const float*)d_in[1];
    const float* b1 = (const float*)d_in[2];
    const float* W2 = (const float*)d_in[3];
    const float* b2 = (const float*)d_in[4];
    const float* W3 = (const float*)d_in[5];
    const float* b3 = (const float*)d_in[6];
    float* out = (float*)d_out;

    const size_t smem_bytes = SMEM_FLOATS * sizeof(float);  // ~213.6 KB
    cudaFuncSetAttribute(ecg_fused_kernel,
                         cudaFuncAttributeMaxDynamicSharedMemorySize,
                         (int)smem_bytes);

    ecg_fused_kernel<<<B_TOTAL / NB, THREADS, smem_bytes>>>(
        x, W1, b1, W2, b2, W3, b3, out);
}